// round 13
// baseline (speedup 1.0000x reference)
#include <cuda_runtime.h>
#include <math.h>
#include <stdint.h>

// ---------------------------------------------------------------------------
// TPAttention: x@Wq/Wk/Wv -> RoPE -> GQA flash attention over KV cache -> @Wo
// B=8 S=4 P=4096 HID=4096 HQ=32 HKV=8 D=128 (M=32). fp32 math, f32x2 FMA.
// R13: GEMM inner loop = pure {3 LDS + 8 FFMA2}; x pre-packed as f32x2 in
//      smem; x+W 3-stage rings, ONE sync per k-tile.
// ---------------------------------------------------------------------------

namespace {
constexpr int cB = 8, cS = 4, cP = 4096, cHQ = 32, cHKV = 8, cD = 128;
constexpr int cM = cB * cS;             // 32
constexpr int cK = 4096;
constexpr int cNQ = cHQ * cD;           // 4096
constexpr int cNKV = cHKV * cD;         // 1024
constexpr int cNTOT = cNQ + 2 * cNKV;   // 6144
constexpr int cT = cP + cS;             // 4100
constexpr int KSPLIT = 8;               // split-K for GEMMs
constexpr int KCHUNK = cK / KSPLIT;     // 512
constexpr int GSTG = 3;                 // GEMM ring stages (x and W)
constexpr int NSPLIT = 4;               // flash-decoding KV splits
constexpr int KBLK = 64;                // keys per super-tile
constexpr int NKB = (cT + KBLK - 1) / KBLK;        // 65
constexpr int KBPS = (NKB + NSPLIT - 1) / NSPLIT;  // 17
constexpr int ATTN_SMEM =
    (16 * 128 + 2 * 64 * 132 + 2 * 32 * 132 + 16 * 68 + 16) * 4;  // 113984
// counters: [0,40) qk heads (16), [40,56) v tiles (8), [56,120) out tiles (8),
//           [120,184) attn bh (NSPLIT)
constexpr int CNT_HEAD = 0, CNT_V = 40, CNT_OUT = 56, CNT_BH = 120;
}  // namespace

typedef unsigned long long ull;

__device__ __forceinline__ ull pack2(float lo, float hi) {
  ull r;
  asm("mov.b64 %0, {%1, %2};" : "=l"(r) : "f"(lo), "f"(hi));
  return r;
}
__device__ __forceinline__ float2 unpack2(ull v) {
  float2 f;
  asm("mov.b64 {%0, %1}, %2;" : "=f"(f.x), "=f"(f.y) : "l"(v));
  return f;
}
__device__ __forceinline__ void ffma2(ull& d, ull a, ull b) {
  asm("fma.rn.f32x2 %0, %1, %2, %0;" : "+l"(d) : "l"(a), "l"(b));
}
__device__ __forceinline__ ull fmul2(ull a, ull b) {
  ull r;
  asm("mul.rn.f32x2 %0, %1, %2;" : "=l"(r) : "l"(a), "l"(b));
  return r;
}
__device__ __forceinline__ ull fadd2(ull a, ull b) {
  ull r;
  asm("add.rn.f32x2 %0, %1, %2;" : "=l"(r) : "l"(a), "l"(b));
  return r;
}
__device__ __forceinline__ void cpa16(uint32_t s, const void* g) {
  asm volatile("cp.async.cg.shared.global [%0], [%1], 16;" :: "r"(s), "l"(g));
}
__device__ __forceinline__ void cpa_commit() {
  asm volatile("cp.async.commit_group;");
}
template <int N>
__device__ __forceinline__ void cpa_wait() {
  asm volatile("cp.async.wait_group %0;" :: "n"(N));
}

__device__ float g_qkvp[KSPLIT][cM * cNTOT];
__device__ float g_q[cM * cHQ * cD];
__device__ float g_kn[cM * cHKV * cD];
__device__ float g_vn[cM * cHKV * cD];
__device__ float g_Op[cB * cHKV * NSPLIT * 16 * cD];
__device__ float g_Ms[cB * cHKV * NSPLIT * 16];
__device__ float g_Ls[cB * cHKV * NSPLIT * 16];
__device__ float g_ao[cM * cNQ];
__device__ float g_outp[KSPLIT][cM * cNQ];
__device__ unsigned int g_cnt[184];   // monotonic; modulo makes replay-safe

__device__ __forceinline__ bool last_arriver(int cidx, unsigned int n,
                                             int tid, unsigned int* flag_s) {
  __threadfence();
  __syncthreads();
  if (tid == 0) {
    const unsigned int old = atomicAdd(&g_cnt[cidx], 1u);
    *flag_s = ((old % n) == n - 1u);
  }
  __syncthreads();
  const bool last = (*flag_s != 0u);
  if (last) __threadfence();
  return last;
}

// ---------------------------------------------------------------------------
// GEMM (f32x2): C_split = A[32 x 4096] @ W, 64-col N tiles, split-K grid.y.
// x pre-duplicated to f32x2 in a 3-stage smem ring (LDG->reg->STS, 2 tiles
// ahead); W in a 3-stage cp.async ring. ONE __syncthreads per 32-k tile.
// Inner loop per kk: 3x LDS.128 + 8x FFMA2. Fused last-CTA epilogues (R11).
// ---------------------------------------------------------------------------
__global__ __launch_bounds__(128) void gemm_f2_kernel(
    const float* __restrict__ A, const float* __restrict__ W0,
    const float* __restrict__ W1, const float* __restrict__ W2,
    float* __restrict__ Cb, int qkv,
    const float* __restrict__ cosb, const float* __restrict__ sinb,
    const int* __restrict__ past_len, float* __restrict__ outp) {
  __shared__ ull xs2[GSTG][32][34];     // [stage][kk][m] duplicated pairs
  __shared__ float ws[GSTG][32][68];
  __shared__ unsigned int flag_s;
  const int tid = threadIdx.x;
  const int bx = blockIdx.x;

  const float* W;
  int ldw, ncol, ldc, csz;
  if (qkv) {
    ldc = cNTOT; csz = cM * cNTOT;
    if (bx < 64)      { W = W0; ldw = cNQ;  ncol = bx * 64; }
    else if (bx < 80) { W = W1; ldw = cNKV; ncol = cNQ + (bx - 64) * 64; }
    else              { W = W2; ldw = cNKV; ncol = cNQ + cNKV + (bx - 80) * 64; }
  } else {
    ldc = cNQ; csz = cM * cNQ;
    W = W0; ldw = cNQ; ncol = bx * 64;
  }
  const int n0w = (qkv ? (ncol - (bx < 64 ? 0 : (bx < 80 ? cNQ : cNQ + cNKV)))
                       : ncol);
  const int k0s = blockIdx.y * KCHUNK;
  float* C = Cb + blockIdx.y * csz;

  const int mg = tid >> 4;
  const int ng = tid & 15;
  const int lm = tid >> 2;
  const int lkv = tid & 3;
  const int wk0 = tid >> 4;
  const int wn = tid & 15;
  const int wgcol = n0w + 4 * wn;

  const uint32_t ws_base = (uint32_t)__cvta_generic_to_shared(ws);
  const int NT = KCHUNK / 32;  // 16

  auto load_wtile = [&](int t) {
    const int stg = t % GSTG;
    const int kt = k0s + 32 * t;
#pragma unroll
    for (int q = 0; q < 4; q++) {
      const uint32_t dst =
          ws_base + (uint32_t)(((stg * 32 + wk0 + 8 * q) * 68 + 4 * wn) * 4);
      cpa16(dst, &W[(kt + wk0 + 8 * q) * ldw + wgcol]);
    }
  };
  auto ldg_x = [&](int t, float4& a, float4& b) {
    const int kt = k0s + 32 * t;
    a = *(const float4*)&A[lm * cK + kt + 4 * lkv];
    b = *(const float4*)&A[lm * cK + kt + 16 + 4 * lkv];
  };
  auto sts_x = [&](int t, const float4& a, const float4& b) {
    const int stg = t % GSTG;
#pragma unroll
    for (int c = 0; c < 4; c++) {
      xs2[stg][4 * lkv + c][lm] = pack2((&a.x)[c], (&a.x)[c]);
      xs2[stg][16 + 4 * lkv + c][lm] = pack2((&b.x)[c], (&b.x)[c]);
    }
  };

  ull acc[4][2] = {};

  // prologue: W tiles 0,1 committed; x tiles 0,1 staged; x tile 2 in regs
  load_wtile(0); cpa_commit();
  load_wtile(1); cpa_commit();
  {
    float4 a0, b0, a1, b1;
    ldg_x(0, a0, b0);
    ldg_x(1, a1, b1);
    sts_x(0, a0, b0);
    sts_x(1, a1, b1);
  }
  float4 xra, xrb;
  ldg_x(2, xra, xrb);

  for (int t = 0; t < NT; t++) {
    const int st = t % GSTG;
    cpa_wait<1>();        // W(t) landed (1 newer group may be pending)
    __syncthreads();      // all warps done with tile t-1; stages visible

#pragma unroll
    for (int kk = 0; kk < 32; kk++) {
      const ulonglong2 xa = *(const ulonglong2*)&xs2[st][kk][4 * mg];
      const ulonglong2 xb = *(const ulonglong2*)&xs2[st][kk][4 * mg + 2];
      const ulonglong2 wv = *(const ulonglong2*)&ws[st][kk][4 * ng];
      ffma2(acc[0][0], xa.x, wv.x); ffma2(acc[0][1], xa.x, wv.y);
      ffma2(acc[1][0], xa.y, wv.x); ffma2(acc[1][1], xa.y, wv.y);
      ffma2(acc[2][0], xb.x, wv.x); ffma2(acc[2][1], xb.x, wv.y);
      ffma2(acc[3][0], xb.y, wv.x); ffma2(acc[3][1], xb.y, wv.y);
    }

    // stage x tile t+2 into ring (stage (t+2)%3 == (t-1)%3, freed by sync)
    if (t + 2 < NT) sts_x(t + 2, xra, xrb);
    // prefetch x tile t+3 into regs
    if (t + 3 < NT) ldg_x(t + 3, xra, xrb);
    // stream W tile t+2; exactly one commit per iteration
    if (t + 2 < NT) load_wtile(t + 2);
    cpa_commit();
  }

#pragma unroll
  for (int i = 0; i < 4; i++) {
    const float2 lo = unpack2(acc[i][0]);
    const float2 hi = unpack2(acc[i][1]);
    float4 o = make_float4(lo.x, lo.y, hi.x, hi.y);
    *(float4*)&C[(4 * mg + i) * ldc + ncol + 4 * ng] = o;
  }

  // ---- fused epilogues (unchanged from R11/R12) ----
  if (qkv) {
    if (bx < 80) {
      const int hh = (bx < 64) ? (bx >> 1) : (32 + ((bx - 64) >> 1));
      if (!last_arriver(CNT_HEAD + hh, 16u, tid, &flag_s)) return;
      const int pos0 = past_len[0];
#pragma unroll
      for (int w = 0; w < 4; w++) {
        const int item = tid + w * 128;
        const int m = item >> 4, dv = item & 15;
        const int d = 4 * dv;
        const int base = m * cNTOT + hh * 128 + d;
        float4 lo = make_float4(0.f, 0.f, 0.f, 0.f);
        float4 hi = make_float4(0.f, 0.f, 0.f, 0.f);
#pragma unroll
        for (int s = 0; s < KSPLIT; s++) {
          const float4 a = *(const float4*)&g_qkvp[s][base];
          const float4 b = *(const float4*)&g_qkvp[s][base + 64];
          lo.x += a.x; lo.y += a.y; lo.z += a.z; lo.w += a.w;
          hi.x += b.x; hi.y += b.y; hi.z += b.z; hi.w += b.w;
        }
        const int pos = pos0 + (m & 3);
        const float4 cl = *(const float4*)&cosb[pos * cD + d];
        const float4 ch = *(const float4*)&cosb[pos * cD + d + 64];
        const float4 sl = *(const float4*)&sinb[pos * cD + d];
        const float4 sh = *(const float4*)&sinb[pos * cD + d + 64];
        float4 olo, ohi;
        olo.x = fmaf(lo.x, cl.x, -hi.x * sl.x);
        olo.y = fmaf(lo.y, cl.y, -hi.y * sl.y);
        olo.z = fmaf(lo.z, cl.z, -hi.z * sl.z);
        olo.w = fmaf(lo.w, cl.w, -hi.w * sl.w);
        ohi.x = fmaf(hi.x, ch.x, lo.x * sh.x);
        ohi.y = fmaf(hi.y, ch.y, lo.y * sh.y);
        ohi.z = fmaf(hi.z, ch.z, lo.z * sh.z);
        ohi.w = fmaf(hi.w, ch.w, lo.w * sh.w);
        if (hh < 32) {
          float* dst = &g_q[(m * cHQ + hh) * cD + d];
          *(float4*)dst = olo;
          *(float4*)(dst + 64) = ohi;
        } else {
          float* dst = &g_kn[(m * cHKV + (hh - 32)) * cD + d];
          *(float4*)dst = olo;
          *(float4*)(dst + 64) = ohi;
        }
      }
    } else {
      const int vt = bx - 80;
      if (!last_arriver(CNT_V + vt, 8u, tid, &flag_s)) return;
#pragma unroll
      for (int w = 0; w < 4; w++) {
        const int item = tid + w * 128;
        const int m = item >> 4, dv = item & 15;
        const int c4 = vt * 64 + 4 * dv;
        const int base = m * cNTOT + cNQ + cNKV + c4;
        float4 v = make_float4(0.f, 0.f, 0.f, 0.f);
#pragma unroll
        for (int s = 0; s < KSPLIT; s++) {
          const float4 a = *(const float4*)&g_qkvp[s][base];
          v.x += a.x; v.y += a.y; v.z += a.z; v.w += a.w;
        }
        *(float4*)&g_vn[(m * cHKV + (c4 >> 7)) * cD + (c4 & 127)] = v;
      }
    }
  } else {
    if (!last_arriver(CNT_OUT + bx, 8u, tid, &flag_s)) return;
#pragma unroll
    for (int w = 0; w < 4; w++) {
      const int item = tid + w * 128;
      const int row = item >> 4, col4 = item & 15;
      const int idx = row * cNQ + ncol + 4 * col4;
      float4 a = make_float4(0.f, 0.f, 0.f, 0.f);
#pragma unroll
      for (int s = 0; s < KSPLIT; s++) {
        const float4 v = *(const float4*)&g_outp[s][idx];
        a.x += v.x; a.y += v.y; a.z += v.z; a.w += v.w;
      }
      *(float4*)&outp[idx] = a;
    }
  }
}

// ---------------------------------------------------------------------------
// Flash-decoding attention (R9/R10 winner) + fused combine epilogue. Unchanged.
// ---------------------------------------------------------------------------
__global__ __launch_bounds__(128) void attn_kernel(
    const float* __restrict__ kc, const float* __restrict__ vc,
    const int* __restrict__ past_len) {
  extern __shared__ float sm[];
  float* qs = sm;                     // [16][128]
  float* ks = qs + 16 * 128;          // [2][64][132]
  float* vs = ks + 2 * 64 * 132;      // [2][32][132]
  float* ps = vs + 2 * 32 * 132;      // [16][68]
  float* fac_s = ps + 16 * 68;        // [16]
  __shared__ unsigned int flag_s;

  const int tid = threadIdx.x;
  const int bh = blockIdx.x;
  const int b = bh >> 3, h = bh & 7;
  const int split = blockIdx.y;
  const int pl = past_len[0];
  const float scale = 0.08838834764831845f;  // 1/sqrt(128)
  const int rg = tid >> 5;
  const int kg = tid & 31;
  const int rh = rg >> 1;
  const int dh = rg & 1;
  const int kh = kg >> 4;
  const int dc = kg & 15;

#pragma unroll
  for (int it = 0; it < 4; it++) {
    const int idx = tid + it * 128;
    const int r = idx >> 5, dv = idx & 31;
    const int s = r >> 2, g = r & 3;
    float4 qv = *(const float4*)&g_q[((b * cS + s) * cHQ + (h * 4 + g)) * cD + 4 * dv];
    qv.x *= scale; qv.y *= scale; qv.z *= scale; qv.w *= scale;
    *(float4*)&qs[r * 128 + 4 * dv] = qv;
  }

  const uint32_t ks_base = (uint32_t)__cvta_generic_to_shared(ks);
  const uint32_t vs_base = (uint32_t)__cvta_generic_to_shared(vs);

  const int kb0 = split * KBPS;
  const int kb1 = (kb0 + KBPS < NKB) ? (kb0 + KBPS) : NKB;
  const int nt = kb1 - kb0;

  auto load_ktile = [&](int kb, int st) {
    const int t0 = kb * KBLK;
    const uint32_t kdst0 = ks_base + (uint32_t)(st * 64 * 132 * 4);
#pragma unroll
    for (int it = 0; it < 16; it++) {
      const int idx = tid + it * 128;
      const int tt = idx >> 5, dv = idx & 31;
      int t = t0 + tt;
      if (t > cT - 1) t = cT - 1;
      const float* src;
      if (t < cP) src = kc + ((b * cP + t) * cHKV + h) * cD + 4 * dv;
      else        src = g_kn + ((b * cS + (t - cP)) * cHKV + h) * cD + 4 * dv;
      cpa16(kdst0 + (uint32_t)((tt * 132 + 4 * dv) * 4), src);
    }
  };
  auto load_vhalf = [&](int kb, int half) {
    const int t0 = kb * KBLK + 32 * half;
    const uint32_t vdst0 = vs_base + (uint32_t)(half * 32 * 132 * 4);
#pragma unroll
    for (int it = 0; it < 8; it++) {
      const int idx = tid + it * 128;
      const int tt = idx >> 5, dv = idx & 31;
      int t = t0 + tt;
      if (t > cT - 1) t = cT - 1;
      const float* src;
      if (t < cP) src = vc + ((b * cP + t) * cHKV + h) * cD + 4 * dv;
      else        src = g_vn + ((b * cS + (t - cP)) * cHKV + h) * cD + 4 * dv;
      cpa16(vdst0 + (uint32_t)((tt * 132 + 4 * dv) * 4), src);
    }
  };

  float mrun[4] = {-1e30f, -1e30f, -1e30f, -1e30f};
  float lrun[4] = {0.f, 0.f, 0.f, 0.f};
  ull o2[8][2] = {};

  load_ktile(kb0, 0); cpa_commit();
  load_vhalf(kb0, 0); cpa_commit();
  load_vhalf(kb0, 1); cpa_commit();
  if (nt > 1) { load_ktile(kb0 + 1, 1); cpa_commit(); }

  for (int i = 0; i < nt; i++) {
    const int st = i & 1;
    const int t0 = (kb0 + i) * KBLK;
    const bool more1 = (i + 1 < nt);

    if (more1) cpa_wait<3>(); else cpa_wait<2>();
    __syncthreads();

    const float* kst = ks + st * 64 * 132;

    ull sc[4][2] = {};
#pragma unroll 8
    for (int dv = 0; dv < 32; dv++) {
      const ulonglong2 k0v = *(const ulonglong2*)&kst[kg * 132 + 4 * dv];
      const ulonglong2 k1v = *(const ulonglong2*)&kst[(kg + 32) * 132 + 4 * dv];
#pragma unroll
      for (int j = 0; j < 4; j++) {
        const ulonglong2 qv = *(const ulonglong2*)&qs[(4 * rg + j) * 128 + 4 * dv];
        ffma2(sc[j][0], qv.x, k0v.x); ffma2(sc[j][0], qv.y, k0v.y);
        ffma2(sc[j][1], qv.x, k1v.x); ffma2(sc[j][1], qv.y, k1v.y);
      }
    }
#pragma unroll
    for (int j = 0; j < 4; j++) {
      const float2 a = unpack2(sc[j][0]);
      const float2 c = unpack2(sc[j][1]);
      float s0 = a.x + a.y;
      float s1 = c.x + c.y;
      if (t0 + kg > pl + rg) s0 = -1e30f;
      if (t0 + kg + 32 > pl + rg) s1 = -1e30f;
      float mx = fmaxf(s0, s1);
#pragma unroll
      for (int w = 16; w; w >>= 1) mx = fmaxf(mx, __shfl_xor_sync(0xffffffffu, mx, w));
      const float mnew = fmaxf(mrun[j], mx);
      const float f = __expf(mrun[j] - mnew);
      const float p0 = (s0 < -1e29f) ? 0.f : __expf(s0 - mnew);
      const float p1 = (s1 < -1e29f) ? 0.f : __expf(s1 - mnew);
      ps[(4 * rg + j) * 68 + kg] = p0;
      ps[(4 * rg + j) * 68 + kg + 32] = p1;
      float ls = p0 + p1;
#pragma unroll
      for (int w = 16; w; w >>= 1) ls += __shfl_xor_sync(0xffffffffu, ls, w);
      lrun[j] = fmaf(lrun[j], f, ls);
      mrun[j] = mnew;
      if (kg == 0) fac_s[4 * rg + j] = f;
    }

    // ---- PV phase a ----
    if (more1) cpa_wait<2>(); else cpa_wait<1>();
    __syncthreads();
    {
#pragma unroll
      for (int j = 0; j < 8; j++) {
        const float fj = fac_s[8 * rh + j];
        const ull ff = pack2(fj, fj);
        o2[j][0] = fmul2(o2[j][0], ff);
        o2[j][1] = fmul2(o2[j][1], ff);
      }
      const float* vsp = vs;
      const int colb = kh * 16;
#pragma unroll
      for (int tg = 0; tg < 4; tg++) {
        float4 p4[8];
#pragma unroll
        for (int j = 0; j < 8; j++)
          p4[j] = *(const float4*)&ps[(8 * rh + j) * 68 + colb + 4 * tg];
#pragma unroll
        for (int u = 0; u < 4; u++) {
          const int tr = kh * 16 + 4 * tg + u;
          const ulonglong2 vv = *(const ulonglong2*)&vsp[tr * 132 + 64 * dh + 4 * dc];
#pragma unroll
          for (int j = 0; j < 8; j++) {
            const float pv = (&p4[j].x)[u];
            const ull pp = pack2(pv, pv);
            ffma2(o2[j][0], pp, vv.x);
            ffma2(o2[j][1], pp, vv.y);
          }
        }
      }
    }
    __syncthreads();
    if (more1) { load_vhalf(kb0 + i + 1, 0); cpa_commit(); }

    // ---- PV phase b ----
    if (more1) cpa_wait<2>(); else cpa_wait<0>();
    __syncthreads();
    {
      const float* vsp = vs + 32 * 132;
      const int colb = 32 + kh * 16;
#pragma unroll
      for (int tg = 0; tg < 4; tg++) {
        float4 p4[8];
#pragma unroll
        for (int j = 0; j < 8; j++)
          p4[j] = *(const float4*)&ps[(8 * rh + j) * 68 + colb + 4 * tg];
#pragma unroll
        for (int u = 0; u < 4; u++) {
          const int tr = kh * 16 + 4 * tg + u;
          const ulonglong2 vv = *(const ulonglong2*)&vsp[tr * 132 + 64 * dh + 4 * dc];
#pragma unroll
          for (int j = 0; j < 8; j++) {
            const float pv = (&p4[j].x)[u];
            const ull pp = pack2(pv, pv);
            ffma2(o2[j][0], pp, vv.x);
            ffma2(o2[j][1], pp, vv.y);
          }
        }
      }
    }
    __syncthreads();
    if (more1) { load_vhalf(kb0 + i + 1, 1); cpa_commit(); }
    if (i + 2 < nt) { load_ktile(kb0 + i + 2, (i + 2) & 1); cpa_commit(); }
  }

  const int base = (bh * NSPLIT + split) * 16;
#pragma unroll
  for (int j = 0; j < 8; j++) {
#pragma unroll
    for (int c = 0; c < 2; c++) {
      const ull oth = __shfl_xor_sync(0xffffffffu, o2[j][c], 16);
      o2[j][c] = fadd2(o2[j][c], oth);
    }
  }
  if (kh == 0) {
#pragma unroll
    for (int j = 0; j < 8; j++) {
      const int r = 8 * rh + j;
      const float2 lo = unpack2(o2[j][0]);
      const float2 hi = unpack2(o2[j][1]);
      float4 o = make_float4(lo.x, lo.y, hi.x, hi.y);
      *(float4*)&g_Op[(base + r) * cD + 64 * dh + 4 * dc] = o;
    }
  }
  if (kg == 0) {
#pragma unroll
    for (int j = 0; j < 4; j++) {
      g_Ms[base + 4 * rg + j] = mrun[j];
      g_Ls[base + 4 * rg + j] = lrun[j];
    }
  }

  if (!last_arriver(CNT_BH + bh, (unsigned)NSPLIT, tid, &flag_s)) return;
  {
    const int cr = tid >> 3;
    const int cq = (tid & 7) * 16;
    const int base0 = bh * NSPLIT;
    float m[NSPLIT], l[NSPLIT];
    float mstar = -1e30f;
#pragma unroll
    for (int i = 0; i < NSPLIT; i++) {
      m[i] = g_Ms[(base0 + i) * 16 + cr];
      l[i] = g_Ls[(base0 + i) * 16 + cr];
      mstar = fmaxf(mstar, m[i]);
    }
    float w[NSPLIT];
    float L = 0.f;
#pragma unroll
    for (int i = 0; i < NSPLIT; i++) {
      w[i] = __expf(m[i] - mstar);
      L = fmaf(w[i], l[i], L);
    }
    const float inv = 1.f / L;
    const int s = cr >> 2, g = cr & 3;
    float* dst = &g_ao[((b * cS + s) * cHQ + (h * 4 + g)) * cD + cq];
#pragma unroll
    for (int c2 = 0; c2 < 4; c2++) {
      float4 a = make_float4(0.f, 0.f, 0.f, 0.f);
#pragma unroll
      for (int i = 0; i < NSPLIT; i++) {
        const float4 ov =
            *(const float4*)&g_Op[((base0 + i) * 16 + cr) * cD + cq + 4 * c2];
        a.x = fmaf(w[i], ov.x, a.x);
        a.y = fmaf(w[i], ov.y, a.y);
        a.z = fmaf(w[i], ov.z, a.z);
        a.w = fmaf(w[i], ov.w, a.w);
      }
      a.x *= inv; a.y *= inv; a.z *= inv; a.w *= inv;
      *(float4*)&dst[4 * c2] = a;
    }
  }
}

// ---------------------------------------------------------------------------
extern "C" void kernel_launch(void* const* d_in, const int* in_sizes, int n_in,
                              void* d_out, int out_size) {
  const float* x = (const float*)d_in[0];
  const float* wq = (const float*)d_in[1];
  const float* wk = (const float*)d_in[2];
  const float* wv = (const float*)d_in[3];
  const float* wo = (const float*)d_in[4];
  const float* cosb = (const float*)d_in[5];
  const float* sinb = (const float*)d_in[6];
  const float* kc = (const float*)d_in[7];
  const float* vc = (const float*)d_in[8];
  const int* pl = (const int*)d_in[9];
  float* out = (float*)d_out;

  float *qkvp, *aop, *outp;
  cudaGetSymbolAddress((void**)&qkvp, g_qkvp);
  cudaGetSymbolAddress((void**)&aop, g_ao);
  cudaGetSymbolAddress((void**)&outp, g_outp);

  // QKV projection + fused (sum+RoPE) epilogue
  gemm_f2_kernel<<<dim3(96, KSPLIT), 128>>>(x, wq, wk, wv, qkvp, 1,
                                            cosb, sinb, pl, nullptr);
  // flash-decoding attention + fused combine epilogue
  cudaFuncSetAttribute(attn_kernel, cudaFuncAttributeMaxDynamicSharedMemorySize, ATTN_SMEM);
  attn_kernel<<<dim3(cB * cHKV, NSPLIT), 128, ATTN_SMEM>>>(kc, vc, pl);
  // output projection + fused sum epilogue -> d_out
  gemm_f2_kernel<<<dim3(64, KSPLIT), 128>>>(aop, wo, wo, wo, outp, 0,
                                            cosb, sinb, pl, out);
}

// round 14
// speedup vs baseline: 1.1594x; 1.1594x over previous
#include <cuda_runtime.h>
#include <math.h>
#include <stdint.h>

// ---------------------------------------------------------------------------
// TPAttention: x@Wq/Wk/Wv -> RoPE -> GQA flash attention over KV cache -> @Wo
// B=8 S=4 P=4096 HID=4096 HQ=32 HKV=8 D=128 (M=32). fp32 math, f32x2 FMA.
// R14: GEMM = R12 champion (4-stage W cp.async ring, float4 x). Attention
//      NSPLIT 4->8 for SM load balance (only change vs R12).
// ---------------------------------------------------------------------------

namespace {
constexpr int cB = 8, cS = 4, cP = 4096, cHQ = 32, cHKV = 8, cD = 128;
constexpr int cM = cB * cS;             // 32
constexpr int cK = 4096;
constexpr int cNQ = cHQ * cD;           // 4096
constexpr int cNKV = cHKV * cD;         // 1024
constexpr int cNTOT = cNQ + 2 * cNKV;   // 6144
constexpr int cT = cP + cS;             // 4100
constexpr int KSPLIT = 8;               // split-K for GEMMs
constexpr int KCHUNK = cK / KSPLIT;     // 512
constexpr int GSTG = 4;                 // W cp.async stages
constexpr int NSPLIT = 8;               // flash-decoding KV splits
constexpr int KBLK = 64;                // keys per super-tile
constexpr int NKB = (cT + KBLK - 1) / KBLK;        // 65
constexpr int KBPS = (NKB + NSPLIT - 1) / NSPLIT;  // 9
constexpr int ATTN_SMEM =
    (16 * 128 + 2 * 64 * 132 + 2 * 32 * 132 + 16 * 68 + 16) * 4;  // 113984
// counters: [0,40) qk heads (16), [40,56) v tiles (8), [56,120) out tiles (8),
//           [120,184) attn bh (NSPLIT)
constexpr int CNT_HEAD = 0, CNT_V = 40, CNT_OUT = 56, CNT_BH = 120;
}  // namespace

typedef unsigned long long ull;

__device__ __forceinline__ ull pack2(float lo, float hi) {
  ull r;
  asm("mov.b64 %0, {%1, %2};" : "=l"(r) : "f"(lo), "f"(hi));
  return r;
}
__device__ __forceinline__ float2 unpack2(ull v) {
  float2 f;
  asm("mov.b64 {%0, %1}, %2;" : "=f"(f.x), "=f"(f.y) : "l"(v));
  return f;
}
__device__ __forceinline__ void ffma2(ull& d, ull a, ull b) {
  asm("fma.rn.f32x2 %0, %1, %2, %0;" : "+l"(d) : "l"(a), "l"(b));
}
__device__ __forceinline__ ull fmul2(ull a, ull b) {
  ull r;
  asm("mul.rn.f32x2 %0, %1, %2;" : "=l"(r) : "l"(a), "l"(b));
  return r;
}
__device__ __forceinline__ ull fadd2(ull a, ull b) {
  ull r;
  asm("add.rn.f32x2 %0, %1, %2;" : "=l"(r) : "l"(a), "l"(b));
  return r;
}
__device__ __forceinline__ void cpa16(uint32_t s, const void* g) {
  asm volatile("cp.async.cg.shared.global [%0], [%1], 16;" :: "r"(s), "l"(g));
}
__device__ __forceinline__ void cpa_commit() {
  asm volatile("cp.async.commit_group;");
}
template <int N>
__device__ __forceinline__ void cpa_wait() {
  asm volatile("cp.async.wait_group %0;" :: "n"(N));
}

__device__ float g_qkvp[KSPLIT][cM * cNTOT];
__device__ float g_q[cM * cHQ * cD];
__device__ float g_kn[cM * cHKV * cD];
__device__ float g_vn[cM * cHKV * cD];
__device__ float g_Op[cB * cHKV * NSPLIT * 16 * cD];
__device__ float g_Ms[cB * cHKV * NSPLIT * 16];
__device__ float g_Ls[cB * cHKV * NSPLIT * 16];
__device__ float g_ao[cM * cNQ];
__device__ float g_outp[KSPLIT][cM * cNQ];
__device__ unsigned int g_cnt[184];   // monotonic; modulo makes replay-safe

__device__ __forceinline__ bool last_arriver(int cidx, unsigned int n,
                                             int tid, unsigned int* flag_s) {
  __threadfence();
  __syncthreads();
  if (tid == 0) {
    const unsigned int old = atomicAdd(&g_cnt[cidx], 1u);
    *flag_s = ((old % n) == n - 1u);
  }
  __syncthreads();
  const bool last = (*flag_s != 0u);
  if (last) __threadfence();
  return last;
}

// ---------------------------------------------------------------------------
// GEMM (f32x2): exact R12 champion. W streamed via 4-stage cp.async ring;
// x float4 register-prefetch + double-buffered smem. Fused last-CTA epilogues.
// ---------------------------------------------------------------------------
__global__ __launch_bounds__(128) void gemm_f2_kernel(
    const float* __restrict__ A, const float* __restrict__ W0,
    const float* __restrict__ W1, const float* __restrict__ W2,
    float* __restrict__ Cb, int qkv,
    const float* __restrict__ cosb, const float* __restrict__ sinb,
    const int* __restrict__ past_len, float* __restrict__ outp) {
  __shared__ float xs[2][32][36];
  __shared__ float ws[GSTG][32][68];
  __shared__ unsigned int flag_s;
  const int tid = threadIdx.x;
  const int bx = blockIdx.x;

  const float* W;
  int ldw, ncol, ldc, csz;
  if (qkv) {
    ldc = cNTOT; csz = cM * cNTOT;
    if (bx < 64)      { W = W0; ldw = cNQ;  ncol = bx * 64; }
    else if (bx < 80) { W = W1; ldw = cNKV; ncol = cNQ + (bx - 64) * 64; }
    else              { W = W2; ldw = cNKV; ncol = cNQ + cNKV + (bx - 80) * 64; }
  } else {
    ldc = cNQ; csz = cM * cNQ;
    W = W0; ldw = cNQ; ncol = bx * 64;
  }
  const int n0w = (qkv ? (ncol - (bx < 64 ? 0 : (bx < 80 ? cNQ : cNQ + cNKV)))
                       : ncol);
  const int k0s = blockIdx.y * KCHUNK;
  float* C = Cb + blockIdx.y * csz;

  const int mg = tid >> 4;
  const int ng = tid & 15;
  const int lm = tid >> 2;
  const int lkv = tid & 3;
  const int wk0 = tid >> 4;
  const int wn = tid & 15;
  const int wgcol = n0w + 4 * wn;

  const uint32_t ws_base = (uint32_t)__cvta_generic_to_shared(ws);
  const int NT = KCHUNK / 32;  // 16

  auto load_wtile = [&](int t) {
    const int stg = t & (GSTG - 1);
    const int kt = k0s + 32 * t;
#pragma unroll
    for (int q = 0; q < 4; q++) {
      const uint32_t dst =
          ws_base + (uint32_t)(((stg * 32 + wk0 + 8 * q) * 68 + 4 * wn) * 4);
      cpa16(dst, &W[(kt + wk0 + 8 * q) * ldw + wgcol]);
    }
  };

  ull acc[4][2] = {};

  load_wtile(0); cpa_commit();
  load_wtile(1); cpa_commit();
  load_wtile(2); cpa_commit();
  {
    float4 xr0 = *(const float4*)&A[lm * cK + k0s + 4 * lkv];
    float4 xr1 = *(const float4*)&A[lm * cK + k0s + 16 + 4 * lkv];
#pragma unroll
    for (int c = 0; c < 4; c++) {
      xs[0][4 * lkv + c][lm] = (&xr0.x)[c];
      xs[0][16 + 4 * lkv + c][lm] = (&xr1.x)[c];
    }
  }

  for (int t = 0; t < NT; t++) {
    const int st4 = t & (GSTG - 1);
    const int st2 = t & 1;
    const bool more = (t + 1 < NT);

    cpa_wait<2>();        // W(t) landed (2 newer groups may be pending)
    __syncthreads();      // xs stage + ws visibility

    float4 xr0, xr1;
    if (more) {
      const int k1 = k0s + 32 * (t + 1);
      xr0 = *(const float4*)&A[lm * cK + k1 + 4 * lkv];
      xr1 = *(const float4*)&A[lm * cK + k1 + 16 + 4 * lkv];
    }

#pragma unroll
    for (int kk = 0; kk < 32; kk++) {
      const float4 xv = *(const float4*)&xs[st2][kk][4 * mg];
      const ulonglong2 wv = *(const ulonglong2*)&ws[st4][kk][4 * ng];
      const ull x0 = pack2(xv.x, xv.x);
      const ull x1 = pack2(xv.y, xv.y);
      const ull x2 = pack2(xv.z, xv.z);
      const ull x3 = pack2(xv.w, xv.w);
      ffma2(acc[0][0], x0, wv.x); ffma2(acc[0][1], x0, wv.y);
      ffma2(acc[1][0], x1, wv.x); ffma2(acc[1][1], x1, wv.y);
      ffma2(acc[2][0], x2, wv.x); ffma2(acc[2][1], x2, wv.y);
      ffma2(acc[3][0], x3, wv.x); ffma2(acc[3][1], x3, wv.y);
    }

    if (more) {
      const int s2 = st2 ^ 1;
#pragma unroll
      for (int c = 0; c < 4; c++) {
        xs[s2][4 * lkv + c][lm] = (&xr0.x)[c];
        xs[s2][16 + 4 * lkv + c][lm] = (&xr1.x)[c];
      }
    }
    __syncthreads();      // ws[st4] fully consumed; safe for stage reuse
    if (t + 3 < NT) load_wtile(t + 3);
    cpa_commit();         // one group per iteration (empty in tail)
  }

#pragma unroll
  for (int i = 0; i < 4; i++) {
    const float2 lo = unpack2(acc[i][0]);
    const float2 hi = unpack2(acc[i][1]);
    float4 o = make_float4(lo.x, lo.y, hi.x, hi.y);
    *(float4*)&C[(4 * mg + i) * ldc + ncol + 4 * ng] = o;
  }

  // ---- fused epilogues (unchanged) ----
  if (qkv) {
    if (bx < 80) {
      const int hh = (bx < 64) ? (bx >> 1) : (32 + ((bx - 64) >> 1));
      if (!last_arriver(CNT_HEAD + hh, 16u, tid, &flag_s)) return;
      const int pos0 = past_len[0];
#pragma unroll
      for (int w = 0; w < 4; w++) {
        const int item = tid + w * 128;
        const int m = item >> 4, dv = item & 15;
        const int d = 4 * dv;
        const int base = m * cNTOT + hh * 128 + d;
        float4 lo = make_float4(0.f, 0.f, 0.f, 0.f);
        float4 hi = make_float4(0.f, 0.f, 0.f, 0.f);
#pragma unroll
        for (int s = 0; s < KSPLIT; s++) {
          const float4 a = *(const float4*)&g_qkvp[s][base];
          const float4 b = *(const float4*)&g_qkvp[s][base + 64];
          lo.x += a.x; lo.y += a.y; lo.z += a.z; lo.w += a.w;
          hi.x += b.x; hi.y += b.y; hi.z += b.z; hi.w += b.w;
        }
        const int pos = pos0 + (m & 3);
        const float4 cl = *(const float4*)&cosb[pos * cD + d];
        const float4 ch = *(const float4*)&cosb[pos * cD + d + 64];
        const float4 sl = *(const float4*)&sinb[pos * cD + d];
        const float4 sh = *(const float4*)&sinb[pos * cD + d + 64];
        float4 olo, ohi;
        olo.x = fmaf(lo.x, cl.x, -hi.x * sl.x);
        olo.y = fmaf(lo.y, cl.y, -hi.y * sl.y);
        olo.z = fmaf(lo.z, cl.z, -hi.z * sl.z);
        olo.w = fmaf(lo.w, cl.w, -hi.w * sl.w);
        ohi.x = fmaf(hi.x, ch.x, lo.x * sh.x);
        ohi.y = fmaf(hi.y, ch.y, lo.y * sh.y);
        ohi.z = fmaf(hi.z, ch.z, lo.z * sh.z);
        ohi.w = fmaf(hi.w, ch.w, lo.w * sh.w);
        if (hh < 32) {
          float* dst = &g_q[(m * cHQ + hh) * cD + d];
          *(float4*)dst = olo;
          *(float4*)(dst + 64) = ohi;
        } else {
          float* dst = &g_kn[(m * cHKV + (hh - 32)) * cD + d];
          *(float4*)dst = olo;
          *(float4*)(dst + 64) = ohi;
        }
      }
    } else {
      const int vt = bx - 80;
      if (!last_arriver(CNT_V + vt, 8u, tid, &flag_s)) return;
#pragma unroll
      for (int w = 0; w < 4; w++) {
        const int item = tid + w * 128;
        const int m = item >> 4, dv = item & 15;
        const int c4 = vt * 64 + 4 * dv;
        const int base = m * cNTOT + cNQ + cNKV + c4;
        float4 v = make_float4(0.f, 0.f, 0.f, 0.f);
#pragma unroll
        for (int s = 0; s < KSPLIT; s++) {
          const float4 a = *(const float4*)&g_qkvp[s][base];
          v.x += a.x; v.y += a.y; v.z += a.z; v.w += a.w;
        }
        *(float4*)&g_vn[(m * cHKV + (c4 >> 7)) * cD + (c4 & 127)] = v;
      }
    }
  } else {
    if (!last_arriver(CNT_OUT + bx, 8u, tid, &flag_s)) return;
#pragma unroll
    for (int w = 0; w < 4; w++) {
      const int item = tid + w * 128;
      const int row = item >> 4, col4 = item & 15;
      const int idx = row * cNQ + ncol + 4 * col4;
      float4 a = make_float4(0.f, 0.f, 0.f, 0.f);
#pragma unroll
      for (int s = 0; s < KSPLIT; s++) {
        const float4 v = *(const float4*)&g_outp[s][idx];
        a.x += v.x; a.y += v.y; a.z += v.z; a.w += v.w;
      }
      *(float4*)&outp[idx] = a;
    }
  }
}

// ---------------------------------------------------------------------------
// Flash-decoding attention (R9/R10 winner) + fused combine epilogue.
// NSPLIT=8 (512 CTAs x 9 tiles) for SM load balance.
// ---------------------------------------------------------------------------
__global__ __launch_bounds__(128) void attn_kernel(
    const float* __restrict__ kc, const float* __restrict__ vc,
    const int* __restrict__ past_len) {
  extern __shared__ float sm[];
  float* qs = sm;                     // [16][128]
  float* ks = qs + 16 * 128;          // [2][64][132]
  float* vs = ks + 2 * 64 * 132;      // [2][32][132]
  float* ps = vs + 2 * 32 * 132;      // [16][68]
  float* fac_s = ps + 16 * 68;        // [16]
  __shared__ unsigned int flag_s;

  const int tid = threadIdx.x;
  const int bh = blockIdx.x;
  const int b = bh >> 3, h = bh & 7;
  const int split = blockIdx.y;
  const int pl = past_len[0];
  const float scale = 0.08838834764831845f;  // 1/sqrt(128)
  const int rg = tid >> 5;
  const int kg = tid & 31;
  const int rh = rg >> 1;
  const int dh = rg & 1;
  const int kh = kg >> 4;
  const int dc = kg & 15;

#pragma unroll
  for (int it = 0; it < 4; it++) {
    const int idx = tid + it * 128;
    const int r = idx >> 5, dv = idx & 31;
    const int s = r >> 2, g = r & 3;
    float4 qv = *(const float4*)&g_q[((b * cS + s) * cHQ + (h * 4 + g)) * cD + 4 * dv];
    qv.x *= scale; qv.y *= scale; qv.z *= scale; qv.w *= scale;
    *(float4*)&qs[r * 128 + 4 * dv] = qv;
  }

  const uint32_t ks_base = (uint32_t)__cvta_generic_to_shared(ks);
  const uint32_t vs_base = (uint32_t)__cvta_generic_to_shared(vs);

  const int kb0 = split * KBPS;
  const int kb1 = (kb0 + KBPS < NKB) ? (kb0 + KBPS) : NKB;
  const int nt = kb1 - kb0;
  if (nt <= 0) return;  // (not hit: 8*9=72>=65, last split has 2)

  auto load_ktile = [&](int kb, int st) {
    const int t0 = kb * KBLK;
    const uint32_t kdst0 = ks_base + (uint32_t)(st * 64 * 132 * 4);
#pragma unroll
    for (int it = 0; it < 16; it++) {
      const int idx = tid + it * 128;
      const int tt = idx >> 5, dv = idx & 31;
      int t = t0 + tt;
      if (t > cT - 1) t = cT - 1;
      const float* src;
      if (t < cP) src = kc + ((b * cP + t) * cHKV + h) * cD + 4 * dv;
      else        src = g_kn + ((b * cS + (t - cP)) * cHKV + h) * cD + 4 * dv;
      cpa16(kdst0 + (uint32_t)((tt * 132 + 4 * dv) * 4), src);
    }
  };
  auto load_vhalf = [&](int kb, int half) {
    const int t0 = kb * KBLK + 32 * half;
    const uint32_t vdst0 = vs_base + (uint32_t)(half * 32 * 132 * 4);
#pragma unroll
    for (int it = 0; it < 8; it++) {
      const int idx = tid + it * 128;
      const int tt = idx >> 5, dv = idx & 31;
      int t = t0 + tt;
      if (t > cT - 1) t = cT - 1;
      const float* src;
      if (t < cP) src = vc + ((b * cP + t) * cHKV + h) * cD + 4 * dv;
      else        src = g_vn + ((b * cS + (t - cP)) * cHKV + h) * cD + 4 * dv;
      cpa16(vdst0 + (uint32_t)((tt * 132 + 4 * dv) * 4), src);
    }
  };

  float mrun[4] = {-1e30f, -1e30f, -1e30f, -1e30f};
  float lrun[4] = {0.f, 0.f, 0.f, 0.f};
  ull o2[8][2] = {};

  load_ktile(kb0, 0); cpa_commit();
  load_vhalf(kb0, 0); cpa_commit();
  load_vhalf(kb0, 1); cpa_commit();
  if (nt > 1) { load_ktile(kb0 + 1, 1); cpa_commit(); }

  for (int i = 0; i < nt; i++) {
    const int st = i & 1;
    const int t0 = (kb0 + i) * KBLK;
    const bool more1 = (i + 1 < nt);

    if (more1) cpa_wait<3>(); else cpa_wait<2>();
    __syncthreads();

    const float* kst = ks + st * 64 * 132;

    ull sc[4][2] = {};
#pragma unroll 8
    for (int dv = 0; dv < 32; dv++) {
      const ulonglong2 k0v = *(const ulonglong2*)&kst[kg * 132 + 4 * dv];
      const ulonglong2 k1v = *(const ulonglong2*)&kst[(kg + 32) * 132 + 4 * dv];
#pragma unroll
      for (int j = 0; j < 4; j++) {
        const ulonglong2 qv = *(const ulonglong2*)&qs[(4 * rg + j) * 128 + 4 * dv];
        ffma2(sc[j][0], qv.x, k0v.x); ffma2(sc[j][0], qv.y, k0v.y);
        ffma2(sc[j][1], qv.x, k1v.x); ffma2(sc[j][1], qv.y, k1v.y);
      }
    }
#pragma unroll
    for (int j = 0; j < 4; j++) {
      const float2 a = unpack2(sc[j][0]);
      const float2 c = unpack2(sc[j][1]);
      float s0 = a.x + a.y;
      float s1 = c.x + c.y;
      if (t0 + kg > pl + rg) s0 = -1e30f;
      if (t0 + kg + 32 > pl + rg) s1 = -1e30f;
      float mx = fmaxf(s0, s1);
#pragma unroll
      for (int w = 16; w; w >>= 1) mx = fmaxf(mx, __shfl_xor_sync(0xffffffffu, mx, w));
      const float mnew = fmaxf(mrun[j], mx);
      const float f = __expf(mrun[j] - mnew);
      const float p0 = (s0 < -1e29f) ? 0.f : __expf(s0 - mnew);
      const float p1 = (s1 < -1e29f) ? 0.f : __expf(s1 - mnew);
      ps[(4 * rg + j) * 68 + kg] = p0;
      ps[(4 * rg + j) * 68 + kg + 32] = p1;
      float ls = p0 + p1;
#pragma unroll
      for (int w = 16; w; w >>= 1) ls += __shfl_xor_sync(0xffffffffu, ls, w);
      lrun[j] = fmaf(lrun[j], f, ls);
      mrun[j] = mnew;
      if (kg == 0) fac_s[4 * rg + j] = f;
    }

    // ---- PV phase a ----
    if (more1) cpa_wait<2>(); else cpa_wait<1>();
    __syncthreads();
    {
#pragma unroll
      for (int j = 0; j < 8; j++) {
        const float fj = fac_s[8 * rh + j];
        const ull ff = pack2(fj, fj);
        o2[j][0] = fmul2(o2[j][0], ff);
        o2[j][1] = fmul2(o2[j][1], ff);
      }
      const float* vsp = vs;
      const int colb = kh * 16;
#pragma unroll
      for (int tg = 0; tg < 4; tg++) {
        float4 p4[8];
#pragma unroll
        for (int j = 0; j < 8; j++)
          p4[j] = *(const float4*)&ps[(8 * rh + j) * 68 + colb + 4 * tg];
#pragma unroll
        for (int u = 0; u < 4; u++) {
          const int tr = kh * 16 + 4 * tg + u;
          const ulonglong2 vv = *(const ulonglong2*)&vsp[tr * 132 + 64 * dh + 4 * dc];
#pragma unroll
          for (int j = 0; j < 8; j++) {
            const float pv = (&p4[j].x)[u];
            const ull pp = pack2(pv, pv);
            ffma2(o2[j][0], pp, vv.x);
            ffma2(o2[j][1], pp, vv.y);
          }
        }
      }
    }
    __syncthreads();
    if (more1) { load_vhalf(kb0 + i + 1, 0); cpa_commit(); }

    // ---- PV phase b ----
    if (more1) cpa_wait<2>(); else cpa_wait<0>();
    __syncthreads();
    {
      const float* vsp = vs + 32 * 132;
      const int colb = 32 + kh * 16;
#pragma unroll
      for (int tg = 0; tg < 4; tg++) {
        float4 p4[8];
#pragma unroll
        for (int j = 0; j < 8; j++)
          p4[j] = *(const float4*)&ps[(8 * rh + j) * 68 + colb + 4 * tg];
#pragma unroll
        for (int u = 0; u < 4; u++) {
          const int tr = kh * 16 + 4 * tg + u;
          const ulonglong2 vv = *(const ulonglong2*)&vsp[tr * 132 + 64 * dh + 4 * dc];
#pragma unroll
          for (int j = 0; j < 8; j++) {
            const float pv = (&p4[j].x)[u];
            const ull pp = pack2(pv, pv);
            ffma2(o2[j][0], pp, vv.x);
            ffma2(o2[j][1], pp, vv.y);
          }
        }
      }
    }
    __syncthreads();
    if (more1) { load_vhalf(kb0 + i + 1, 1); cpa_commit(); }
    if (i + 2 < nt) { load_ktile(kb0 + i + 2, (i + 2) & 1); cpa_commit(); }
  }

  const int base = (bh * NSPLIT + split) * 16;
#pragma unroll
  for (int j = 0; j < 8; j++) {
#pragma unroll
    for (int c = 0; c < 2; c++) {
      const ull oth = __shfl_xor_sync(0xffffffffu, o2[j][c], 16);
      o2[j][c] = fadd2(o2[j][c], oth);
    }
  }
  if (kh == 0) {
#pragma unroll
    for (int j = 0; j < 8; j++) {
      const int r = 8 * rh + j;
      const float2 lo = unpack2(o2[j][0]);
      const float2 hi = unpack2(o2[j][1]);
      float4 o = make_float4(lo.x, lo.y, hi.x, hi.y);
      *(float4*)&g_Op[(base + r) * cD + 64 * dh + 4 * dc] = o;
    }
  }
  if (kg == 0) {
#pragma unroll
    for (int j = 0; j < 4; j++) {
      g_Ms[base + 4 * rg + j] = mrun[j];
      g_Ls[base + 4 * rg + j] = lrun[j];
    }
  }

  if (!last_arriver(CNT_BH + bh, (unsigned)NSPLIT, tid, &flag_s)) return;
  {
    const int cr = tid >> 3;
    const int cq = (tid & 7) * 16;
    const int base0 = bh * NSPLIT;
    float m[NSPLIT], l[NSPLIT];
    float mstar = -1e30f;
#pragma unroll
    for (int i = 0; i < NSPLIT; i++) {
      m[i] = g_Ms[(base0 + i) * 16 + cr];
      l[i] = g_Ls[(base0 + i) * 16 + cr];
      mstar = fmaxf(mstar, m[i]);
    }
    float w[NSPLIT];
    float L = 0.f;
#pragma unroll
    for (int i = 0; i < NSPLIT; i++) {
      w[i] = __expf(m[i] - mstar);
      L = fmaf(w[i], l[i], L);
    }
    const float inv = 1.f / L;
    const int s = cr >> 2, g = cr & 3;
    float* dst = &g_ao[((b * cS + s) * cHQ + (h * 4 + g)) * cD + cq];
#pragma unroll
    for (int c2 = 0; c2 < 4; c2++) {
      float4 a = make_float4(0.f, 0.f, 0.f, 0.f);
#pragma unroll
      for (int i = 0; i < NSPLIT; i++) {
        const float4 ov =
            *(const float4*)&g_Op[((base0 + i) * 16 + cr) * cD + cq + 4 * c2];
        a.x = fmaf(w[i], ov.x, a.x);
        a.y = fmaf(w[i], ov.y, a.y);
        a.z = fmaf(w[i], ov.z, a.z);
        a.w = fmaf(w[i], ov.w, a.w);
      }
      a.x *= inv; a.y *= inv; a.z *= inv; a.w *= inv;
      *(float4*)&dst[4 * c2] = a;
    }
  }
}

// ---------------------------------------------------------------------------
extern "C" void kernel_launch(void* const* d_in, const int* in_sizes, int n_in,
                              void* d_out, int out_size) {
  const float* x = (const float*)d_in[0];
  const float* wq = (const float*)d_in[1];
  const float* wk = (const float*)d_in[2];
  const float* wv = (const float*)d_in[3];
  const float* wo = (const float*)d_in[4];
  const float* cosb = (const float*)d_in[5];
  const float* sinb = (const float*)d_in[6];
  const float* kc = (const float*)d_in[7];
  const float* vc = (const float*)d_in[8];
  const int* pl = (const int*)d_in[9];
  float* out = (float*)d_out;

  float *qkvp, *aop, *outp;
  cudaGetSymbolAddress((void**)&qkvp, g_qkvp);
  cudaGetSymbolAddress((void**)&aop, g_ao);
  cudaGetSymbolAddress((void**)&outp, g_outp);

  // QKV projection + fused (sum+RoPE) epilogue
  gemm_f2_kernel<<<dim3(96, KSPLIT), 128>>>(x, wq, wk, wv, qkvp, 1,
                                            cosb, sinb, pl, nullptr);
  // flash-decoding attention + fused combine epilogue (8 splits)
  cudaFuncSetAttribute(attn_kernel, cudaFuncAttributeMaxDynamicSharedMemorySize, ATTN_SMEM);
  attn_kernel<<<dim3(cB * cHKV, NSPLIT), 128, ATTN_SMEM>>>(kc, vc, pl);
  // output projection + fused sum epilogue -> d_out
  gemm_f2_kernel<<<dim3(64, KSPLIT), 128>>>(aop, wo, wo, wo, outp, 0,
                                            cosb, sinb, pl, out);
}